// round 4
// baseline (speedup 1.0000x reference)
#include <cuda_runtime.h>
#include <cuda_bf16.h>

// Problem constants
#define N1M1 4096          // N1 - 1 (columns of b / y)
#define N2   8192          // rows of b / y
#define ROWS 8191          // n2 - 1 rows contribute
#define COLS 4094          // n1 - 2 columns contribute
#define THREADS 256
#define GX 4               // ceil(4094 / (256*4)) = 4
#define NPART (GX * ROWS)  // 32764 block partials

__device__ float g_partials[GX * ROWS];

__global__ __launch_bounds__(THREADS)
void rosen_partial_kernel(const float* __restrict__ x,
                          const float* __restrict__ b)
{
    const int i  = blockIdx.y;                                // row 0..8190
    const int j0 = (blockIdx.x * THREADS + threadIdx.x) * 4;  // column start
    const long base = (long)i * N1M1;                          // row base in x (pre-shift) and b

    float sum = 0.0f;
    if (j0 < COLS) {
        // prev[k] = x[base + j0 + k]  (k = 0..3), except the j==0 wrap
        // cur[k]  = x[base + j0 + k + 1]
        const float4 f0 = *reinterpret_cast<const float4*>(x + base + j0);
        const float4 f1 = *reinterpret_cast<const float4*>(x + base + j0 + 4);
        const float4 bb = *reinterpret_cast<const float4*>(b + base + j0);

        float p0 = f0.x, p1 = f0.y, p2 = f0.z, p3 = f0.w;
        float c0 = f0.y, c1 = f0.z, c2 = f0.w, c3 = f1.x;

        if (j0 == 0) {
            // y_prev[i,0] = y[i, 4095] = x[1 + base + 4095] = x[base + 4096]
            p0 = x[base + N1M1];
        }

        float t;
        t = c0 - p0 * p0;                   sum += bb.x * t * t;   // j0+0 < 4094 always
        t = c1 - p1 * p1; if (j0 + 1 < COLS) sum += bb.y * t * t;
        t = c2 - p2 * p2; if (j0 + 2 < COLS) sum += bb.z * t * t;
        t = c3 - p3 * p3; if (j0 + 3 < COLS) sum += bb.w * t * t;
    }

    // warp tree reduce
    #pragma unroll
    for (int off = 16; off > 0; off >>= 1)
        sum += __shfl_xor_sync(0xFFFFFFFFu, sum, off);

    // block reduce across 8 warps
    __shared__ float s[THREADS / 32];
    const int lane = threadIdx.x & 31;
    const int wid  = threadIdx.x >> 5;
    if (lane == 0) s[wid] = sum;
    __syncthreads();
    if (wid == 0) {
        float v = (lane < THREADS / 32) ? s[lane] : 0.0f;
        #pragma unroll
        for (int off = 4; off > 0; off >>= 1)
            v += __shfl_xor_sync(0xFFFFFFFFu, v, off);
        if (lane == 0)
            g_partials[blockIdx.y * GX + blockIdx.x] = v;
    }
}

__global__ __launch_bounds__(1024)
void rosen_final_kernel(const float* __restrict__ x,
                        const float* __restrict__ a,
                        const float* __restrict__ mu,
                        float* __restrict__ out)
{
    const int tid = threadIdx.x;
    float sum = 0.0f;
    for (int t = tid; t < NPART; t += 1024)
        sum += g_partials[t];

    // warp reduce
    #pragma unroll
    for (int off = 16; off > 0; off >>= 1)
        sum += __shfl_xor_sync(0xFFFFFFFFu, sum, off);

    __shared__ float s[32];
    const int lane = tid & 31;
    const int wid  = tid >> 5;
    if (lane == 0) s[wid] = sum;
    __syncthreads();
    if (wid == 0) {
        float v = (lane < 32) ? s[lane] : 0.0f;
        #pragma unroll
        for (int off = 16; off > 0; off >>= 1)
            v += __shfl_xor_sync(0xFFFFFFFFu, v, off);
        if (lane == 0) {
            const float d = x[0] - mu[0];
            out[0] = -a[0] * d * d - v;
        }
    }
}

extern "C" void kernel_launch(void* const* d_in, const int* in_sizes, int n_in,
                              void* d_out, int out_size)
{
    const float* x  = (const float*)d_in[0];
    const float* a  = (const float*)d_in[1];
    const float* b  = (const float*)d_in[2];
    const float* mu = (const float*)d_in[3];
    float* out = (float*)d_out;

    dim3 grid(GX, ROWS);
    rosen_partial_kernel<<<grid, THREADS>>>(x, b);
    rosen_final_kernel<<<1, 1024>>>(x, a, mu, out);
}

// round 5
// speedup vs baseline: 1.0047x; 1.0047x over previous
#include <cuda_runtime.h>
#include <cuda_bf16.h>

// Problem constants
#define N1M1 4096          // N1 - 1 (columns of b / y)
#define ROWS 8191          // n2 - 1 rows contribute
#define COLS 4094          // n1 - 2 columns contribute
#define THREADS 256
#define GX 4               // tiles per row: 4 * 256 * 4 = 4096 >= 4094
#define NUNITS (GX * ROWS) // 32764 (row, tile) work units
#define GBLOCKS 1184       // 148 SMs * 8 blocks -> single wave

__device__ float        g_partials[GBLOCKS];
__device__ unsigned int g_count = 0;

__global__ __launch_bounds__(THREADS)
void rosen_fused_kernel(const float* __restrict__ x,
                        const float* __restrict__ a,
                        const float* __restrict__ b,
                        const float* __restrict__ mu,
                        float* __restrict__ out)
{
    const int tid  = threadIdx.x;
    const int lane = tid & 31;
    const int wid  = tid >> 5;

    float sum = 0.0f;

    // Grid-stride over (row, tile) units; accumulate in-register.
    for (int u = blockIdx.x; u < NUNITS; u += GBLOCKS) {
        const int  i    = u >> 2;                    // row 0..8190
        const int  t    = u & 3;                     // tile in row
        const int  j0   = ((t << 8) + tid) << 2;     // column start (0..4092)
        const long base = (long)i * N1M1;

        // prev[k] = x[base + j0 + k], cur[k] = x[base + j0 + k + 1]
        const float4 f0 = *reinterpret_cast<const float4*>(x + base + j0);
        const float4 f1 = *reinterpret_cast<const float4*>(x + base + j0 + 4);
        const float4 bb = *reinterpret_cast<const float4*>(b + base + j0);

        float p0 = f0.x;
        const float p1 = f0.y, p2 = f0.z, p3 = f0.w;
        const float c0 = f0.y, c1 = f0.z, c2 = f0.w, c3 = f1.x;

        if (j0 == 0) {
            // roll wrap: y_prev[i,0] = y[i,4095] = x[base + 4096]
            p0 = x[base + N1M1];
        }

        float d;
        d = c0 - p0 * p0;                    sum += bb.x * d * d;   // j0   <= 4092 < 4094
        d = c1 - p1 * p1;                    sum += bb.y * d * d;   // j0+1 <= 4093 < 4094
        d = c2 - p2 * p2; if (j0 + 2 < COLS) sum += bb.z * d * d;
        d = c3 - p3 * p3; if (j0 + 3 < COLS) sum += bb.w * d * d;
    }

    // Warp tree reduce
    #pragma unroll
    for (int off = 16; off > 0; off >>= 1)
        sum += __shfl_xor_sync(0xFFFFFFFFu, sum, off);

    // Block reduce across 8 warps
    __shared__ float s[THREADS / 32];
    __shared__ bool  s_last;
    if (lane == 0) s[wid] = sum;
    __syncthreads();
    if (wid == 0) {
        float v = (lane < THREADS / 32) ? s[lane] : 0.0f;
        #pragma unroll
        for (int off = 4; off > 0; off >>= 1)
            v += __shfl_xor_sync(0xFFFFFFFFu, v, off);
        if (lane == 0) {
            g_partials[blockIdx.x] = v;
            __threadfence();
            const unsigned int prev = atomicAdd(&g_count, 1u);
            s_last = (prev == GBLOCKS - 1);
        }
    }
    __syncthreads();

    // Last-arriving block: deterministic final reduction (fixed order).
    if (s_last) {
        float v = 0.0f;
        for (int t = tid; t < GBLOCKS; t += THREADS)
            v += g_partials[t];

        #pragma unroll
        for (int off = 16; off > 0; off >>= 1)
            v += __shfl_xor_sync(0xFFFFFFFFu, v, off);

        if (lane == 0) s[wid] = v;
        __syncthreads();
        if (wid == 0) {
            float w = (lane < THREADS / 32) ? s[lane] : 0.0f;
            #pragma unroll
            for (int off = 4; off > 0; off >>= 1)
                w += __shfl_xor_sync(0xFFFFFFFFu, w, off);
            if (lane == 0) {
                const float dd = x[0] - mu[0];
                out[0] = -a[0] * dd * dd - w;
                g_count = 0;   // reset for next graph replay
            }
        }
    }
}

extern "C" void kernel_launch(void* const* d_in, const int* in_sizes, int n_in,
                              void* d_out, int out_size)
{
    const float* x  = (const float*)d_in[0];
    const float* a  = (const float*)d_in[1];
    const float* b  = (const float*)d_in[2];
    const float* mu = (const float*)d_in[3];
    float* out = (float*)d_out;

    rosen_fused_kernel<<<GBLOCKS, THREADS>>>(x, a, b, mu, out);
}